// round 1
// baseline (speedup 1.0000x reference)
#include <cuda_runtime.h>
#include <cuda_bf16.h>

// Problem shape (fixed by the dataset): N tokens x D model
#define N_TOK 4096
#define D_MODEL 1024

// Scratch (allocation-free rule: __device__ globals)
__device__ float g_Q[(size_t)N_TOK * D_MODEL];
__device__ float g_K[(size_t)N_TOK * D_MODEL];
__device__ float g_V[(size_t)N_TOK * D_MODEL];
__device__ float g_S[(size_t)N_TOK * N_TOK];

// ---------------------------------------------------------------------------
// Tiled SGEMM: C[M,N] = alpha * A @ op(B) (+ bias[col])
//   BT=true : B is [N,K] row-major, compute A @ B^T   (x@W^T, K@Q^T)
//   BT=false: B is [K,N] row-major, compute A @ B     (P@V)
// BM=BN=128, BK=16, 256 threads, 8x8 microtile per thread.
// ---------------------------------------------------------------------------
#define BM 128
#define BN 128
#define BK 16
#define TM 8
#define TN 8

template <bool BT, bool HAS_BIAS>
__global__ __launch_bounds__(256, 2)
void gemm_kernel(const float* __restrict__ A, const float* __restrict__ B,
                 const float* __restrict__ bias, float* __restrict__ C,
                 int M, int N, int K, float alpha) {
    __shared__ float As[BK][BM];
    __shared__ float Bs[BK][BN];

    const int tid = threadIdx.x;
    const int bm = blockIdx.y * BM;
    const int bn = blockIdx.x * BN;
    const int ty = tid / 16;   // 0..15
    const int tx = tid % 16;   // 0..15

    float acc[TM][TN];
    #pragma unroll
    for (int i = 0; i < TM; i++)
        #pragma unroll
        for (int j = 0; j < TN; j++) acc[i][j] = 0.f;

    for (int k0 = 0; k0 < K; k0 += BK) {
        // ---- load A tile: rows [bm, bm+128), cols [k0, k0+16) -> As[k][m]
        {
            const int r  = tid / 4;          // 0..63
            const int c4 = (tid % 4) * 4;    // 0,4,8,12
            #pragma unroll
            for (int i = 0; i < 2; i++) {
                const int row = r + i * 64;
                const float4 v = *(const float4*)&A[(size_t)(bm + row) * K + k0 + c4];
                As[c4 + 0][row] = v.x;
                As[c4 + 1][row] = v.y;
                As[c4 + 2][row] = v.z;
                As[c4 + 3][row] = v.w;
            }
        }
        // ---- load B tile -> Bs[k][n]
        if (BT) {
            // B is [N,K]: rows [bn, bn+128), cols [k0, k0+16)
            const int r  = tid / 4;
            const int c4 = (tid % 4) * 4;
            #pragma unroll
            for (int i = 0; i < 2; i++) {
                const int row = r + i * 64;
                const float4 v = *(const float4*)&B[(size_t)(bn + row) * K + k0 + c4];
                Bs[c4 + 0][row] = v.x;
                Bs[c4 + 1][row] = v.y;
                Bs[c4 + 2][row] = v.z;
                Bs[c4 + 3][row] = v.w;
            }
        } else {
            // B is [K,N]: rows [k0, k0+16), cols [bn, bn+128)
            const int r  = tid / 32;          // 0..7
            const int c4 = (tid % 32) * 4;    // 0..124
            #pragma unroll
            for (int i = 0; i < 2; i++) {
                const int row = r + i * 8;
                const float4 v = *(const float4*)&B[(size_t)(k0 + row) * N + bn + c4];
                *(float4*)&Bs[row][c4] = v;
            }
        }
        __syncthreads();

        #pragma unroll
        for (int k = 0; k < BK; k++) {
            float a[TM], b[TN];
            #pragma unroll
            for (int i = 0; i < TM; i++) a[i] = As[k][ty * TM + i];
            #pragma unroll
            for (int j = 0; j < TN; j++) b[j] = Bs[k][tx * TN + j];
            #pragma unroll
            for (int i = 0; i < TM; i++)
                #pragma unroll
                for (int j = 0; j < TN; j++)
                    acc[i][j] = fmaf(a[i], b[j], acc[i][j]);
        }
        __syncthreads();
    }

    // ---- epilogue
    #pragma unroll
    for (int i = 0; i < TM; i++) {
        const int row = bm + ty * TM + i;
        float* cp = C + (size_t)row * N + bn + tx * TN;
        #pragma unroll
        for (int j = 0; j < TN; j += 4) {
            float4 v;
            v.x = acc[i][j + 0] * alpha;
            v.y = acc[i][j + 1] * alpha;
            v.z = acc[i][j + 2] * alpha;
            v.w = acc[i][j + 3] * alpha;
            if (HAS_BIAS) {
                const int col = bn + tx * TN + j;
                v.x += bias[col + 0];
                v.y += bias[col + 1];
                v.z += bias[col + 2];
                v.w += bias[col + 3];
            }
            *(float4*)&cp[j] = v;
        }
    }
}

// ---------------------------------------------------------------------------
// Row softmax over S[N_TOK, N_TOK], in place. One block per row.
// 256 threads x 16 values/thread, all register-resident.
// ---------------------------------------------------------------------------
__global__ __launch_bounds__(256)
void softmax_kernel(float* __restrict__ S) {
    constexpr int T = 256;
    constexpr int VPT = N_TOK / T;   // 16
    const int row = blockIdx.x;
    const int tid = threadIdx.x;
    float* p = S + (size_t)row * N_TOK;

    float v[VPT];
    float m = -3.0e38f;
    #pragma unroll
    for (int i = 0; i < VPT; i++) {
        v[i] = p[tid + i * T];
        m = fmaxf(m, v[i]);
    }

    __shared__ float red[T];
    red[tid] = m;
    __syncthreads();
    #pragma unroll
    for (int s = T / 2; s > 0; s >>= 1) {
        if (tid < s) red[tid] = fmaxf(red[tid], red[tid + s]);
        __syncthreads();
    }
    m = red[0];
    __syncthreads();

    float sum = 0.f;
    #pragma unroll
    for (int i = 0; i < VPT; i++) {
        v[i] = __expf(v[i] - m);
        sum += v[i];
    }
    red[tid] = sum;
    __syncthreads();
    #pragma unroll
    for (int s = T / 2; s > 0; s >>= 1) {
        if (tid < s) red[tid] += red[tid + s];
        __syncthreads();
    }
    const float inv = 1.f / red[0];
    #pragma unroll
    for (int i = 0; i < VPT; i++) p[tid + i * T] = v[i] * inv;
}

// ---------------------------------------------------------------------------
// Launch
// ---------------------------------------------------------------------------
extern "C" void kernel_launch(void* const* d_in, const int* in_sizes, int n_in,
                              void* d_out, int out_size) {
    const float* x  = (const float*)d_in[0];
    const float* W1 = (const float*)d_in[1];
    const float* b1 = (const float*)d_in[2];
    const float* W2 = (const float*)d_in[3];
    const float* b2 = (const float*)d_in[4];
    const float* W3 = (const float*)d_in[5];
    const float* b3 = (const float*)d_in[6];
    float* out = (float*)d_out;

    float *Q, *K, *V, *S;
    cudaGetSymbolAddress((void**)&Q, g_Q);
    cudaGetSymbolAddress((void**)&K, g_K);
    cudaGetSymbolAddress((void**)&V, g_V);
    cudaGetSymbolAddress((void**)&S, g_S);

    const dim3 blk(256);
    const dim3 grid_proj(D_MODEL / BN, N_TOK / BM);   // (8, 32)
    const dim3 grid_attn(N_TOK / BN, N_TOK / BM);     // (32, 32)

    // Q = x @ W1^T + b1, K = x @ W2^T + b2, V = x @ W3^T + b3
    gemm_kernel<true, true><<<grid_proj, blk>>>(x, W1, b1, Q, N_TOK, D_MODEL, D_MODEL, 1.f);
    gemm_kernel<true, true><<<grid_proj, blk>>>(x, W2, b2, K, N_TOK, D_MODEL, D_MODEL, 1.f);
    gemm_kernel<true, true><<<grid_proj, blk>>>(x, W3, b3, V, N_TOK, D_MODEL, D_MODEL, 1.f);

    // S = (1/sqrt(D_OUT)) * K @ Q^T    (note: faithful to reference, K rows x Q rows)
    const float scale = rsqrtf((float)D_MODEL);
    gemm_kernel<true, false><<<grid_attn, blk>>>(K, Q, nullptr, S, N_TOK, N_TOK, D_MODEL, scale);

    // row softmax in place
    softmax_kernel<<<N_TOK, blk>>>(S);

    // out = S @ V
    gemm_kernel<false, false><<<grid_proj, blk>>>(S, V, nullptr, out, N_TOK, D_MODEL, N_TOK, 1.f);
}

// round 2
// speedup vs baseline: 3.4217x; 3.4217x over previous
#include <cuda_runtime.h>
#include <cuda_bf16.h>
#include <cstdint>

#define N_TOK 4096
#define D_MODEL 1024

// ---------------------------------------------------------------------------
// Scratch (__device__ globals; no allocations allowed)
// ---------------------------------------------------------------------------
__device__ __nv_bfloat16 g_xh[(size_t)N_TOK * D_MODEL];
__device__ __nv_bfloat16 g_xl[(size_t)N_TOK * D_MODEL];
__device__ __nv_bfloat16 g_w1h[(size_t)D_MODEL * D_MODEL];
__device__ __nv_bfloat16 g_w1l[(size_t)D_MODEL * D_MODEL];
__device__ __nv_bfloat16 g_w2h[(size_t)D_MODEL * D_MODEL];
__device__ __nv_bfloat16 g_w2l[(size_t)D_MODEL * D_MODEL];
__device__ __nv_bfloat16 g_w3h[(size_t)D_MODEL * D_MODEL];
__device__ __nv_bfloat16 g_w3l[(size_t)D_MODEL * D_MODEL];
__device__ __nv_bfloat16 g_qh[(size_t)N_TOK * D_MODEL];
__device__ __nv_bfloat16 g_ql[(size_t)N_TOK * D_MODEL];
__device__ __nv_bfloat16 g_kh[(size_t)N_TOK * D_MODEL];
__device__ __nv_bfloat16 g_kl[(size_t)N_TOK * D_MODEL];
__device__ __nv_bfloat16 g_vh[(size_t)N_TOK * D_MODEL];
__device__ __nv_bfloat16 g_vl[(size_t)N_TOK * D_MODEL];
__device__ float         g_S [(size_t)N_TOK * N_TOK];
__device__ __nv_bfloat16 g_sh[(size_t)N_TOK * N_TOK];
__device__ __nv_bfloat16 g_sl[(size_t)N_TOK * N_TOK];

// ---------------------------------------------------------------------------
// PTX helpers
// ---------------------------------------------------------------------------
__device__ __forceinline__ uint32_t smem_u32(const void* p) {
    return (uint32_t)__cvta_generic_to_shared(p);
}
__device__ __forceinline__ void cp_async16(uint32_t dst, const void* src) {
    asm volatile("cp.async.cg.shared.global [%0], [%1], 16;\n" :: "r"(dst), "l"(src));
}
__device__ __forceinline__ void cp_commit() {
    asm volatile("cp.async.commit_group;\n" ::: "memory");
}
template <int N>
__device__ __forceinline__ void cp_wait() {
    asm volatile("cp.async.wait_group %0;\n" :: "n"(N) : "memory");
}
__device__ __forceinline__ void ldsm_x4(uint32_t& r0, uint32_t& r1, uint32_t& r2, uint32_t& r3,
                                        uint32_t addr) {
    asm volatile("ldmatrix.sync.aligned.m8n8.x4.shared.b16 {%0,%1,%2,%3}, [%4];\n"
                 : "=r"(r0), "=r"(r1), "=r"(r2), "=r"(r3) : "r"(addr));
}
__device__ __forceinline__ void ldsm_x4_t(uint32_t& r0, uint32_t& r1, uint32_t& r2, uint32_t& r3,
                                          uint32_t addr) {
    asm volatile("ldmatrix.sync.aligned.m8n8.x4.trans.shared.b16 {%0,%1,%2,%3}, [%4];\n"
                 : "=r"(r0), "=r"(r1), "=r"(r2), "=r"(r3) : "r"(addr));
}
__device__ __forceinline__ void mma16816(float* c, const uint32_t* a, const uint32_t* b) {
    asm volatile(
        "mma.sync.aligned.m16n8k16.row.col.f32.bf16.bf16.f32 "
        "{%0,%1,%2,%3}, {%4,%5,%6,%7}, {%8,%9}, {%0,%1,%2,%3};\n"
        : "+f"(c[0]), "+f"(c[1]), "+f"(c[2]), "+f"(c[3])
        : "r"(a[0]), "r"(a[1]), "r"(a[2]), "r"(a[3]), "r"(b[0]), "r"(b[1]));
}

// ---------------------------------------------------------------------------
// Split fp32 -> (hi, lo) bf16
// ---------------------------------------------------------------------------
__global__ __launch_bounds__(256)
void split_kernel(const float* __restrict__ in, __nv_bfloat16* __restrict__ hi,
                  __nv_bfloat16* __restrict__ lo, int n4) {
    int i = blockIdx.x * blockDim.x + threadIdx.x;
    if (i >= n4) return;
    float4 v = ((const float4*)in)[i];
    __nv_bfloat16 h0 = __float2bfloat16(v.x);
    __nv_bfloat16 h1 = __float2bfloat16(v.y);
    __nv_bfloat16 h2 = __float2bfloat16(v.z);
    __nv_bfloat16 h3 = __float2bfloat16(v.w);
    __nv_bfloat16 l0 = __float2bfloat16(v.x - __bfloat162float(h0));
    __nv_bfloat16 l1 = __float2bfloat16(v.y - __bfloat162float(h1));
    __nv_bfloat16 l2 = __float2bfloat16(v.z - __bfloat162float(h2));
    __nv_bfloat16 l3 = __float2bfloat16(v.w - __bfloat162float(h3));
    ((__nv_bfloat162*)hi)[2 * i + 0] = __halves2bfloat162(h0, h1);
    ((__nv_bfloat162*)hi)[2 * i + 1] = __halves2bfloat162(h2, h3);
    ((__nv_bfloat162*)lo)[2 * i + 0] = __halves2bfloat162(l0, l1);
    ((__nv_bfloat162*)lo)[2 * i + 1] = __halves2bfloat162(l2, l3);
}

// ---------------------------------------------------------------------------
// Split-bf16 tensor-core GEMM.
//   C[M,Ncols] = alpha * A @ op(B) (+ bias)
//   A given as hi/lo bf16 [M,Kdim] row-major.
//   BT=true : B hi/lo is [Ncols,Kdim] row-major (A @ B^T)
//   BT=false: B hi/lo is [Kdim,Ncols] row-major (A @ B)
//   Output: optional fp32 C, optional bf16 hi/lo C.
// Block 128x128, 8 warps (warp tile 64x32), BK=16, double-buffered cp.async.
// ---------------------------------------------------------------------------
template <bool BT, bool HAS_BIAS, bool WF32, bool WBF16>
__global__ __launch_bounds__(256, 1)
void mma_gemm(const __nv_bfloat16* __restrict__ Ah, const __nv_bfloat16* __restrict__ Al,
              const __nv_bfloat16* __restrict__ Bh, const __nv_bfloat16* __restrict__ Bl,
              const float* __restrict__ bias, float* __restrict__ Cf,
              __nv_bfloat16* __restrict__ Ch, __nv_bfloat16* __restrict__ Cl,
              int M, int Ncols, int Kdim, float alpha) {
    // per-stage arrays: [Ah, Al, Bh, Bl], each 3072 halves (6144 B)
    __shared__ __nv_bfloat16 sm[2][4][3072];

    const int tid  = threadIdx.x;
    const int lane = tid & 31;
    const int wid  = tid >> 5;
    const int wm   = (wid >> 2) * 64;  // warp row base within block tile
    const int wn   = (wid & 3) * 32;   // warp col base within block tile
    const int bm   = blockIdx.y * 128;
    const int bn   = blockIdx.x * 128;

    float acc[4][4][4];
#pragma unroll
    for (int i = 0; i < 4; i++)
#pragma unroll
        for (int j = 0; j < 4; j++)
#pragma unroll
            for (int k = 0; k < 4; k++) acc[i][j][k] = 0.f;

    // gmem load assignments (one 16B cp.async per thread per array per chunk)
    const __nv_bfloat16* aph = Ah + (size_t)(bm + (tid >> 1)) * Kdim + (tid & 1) * 8;
    const __nv_bfloat16* apl = Al + (size_t)(bm + (tid >> 1)) * Kdim + (tid & 1) * 8;
    const uint32_t a_dst = (uint32_t)(((tid >> 1) * 24 + (tid & 1) * 8) * 2);

    const __nv_bfloat16 *bph, *bpl;
    uint32_t b_dst;
    size_t b_step;
    if (BT) {
        bph = Bh + (size_t)(bn + (tid >> 1)) * Kdim + (tid & 1) * 8;
        bpl = Bl + (size_t)(bn + (tid >> 1)) * Kdim + (tid & 1) * 8;
        b_dst = (uint32_t)(((tid >> 1) * 24 + (tid & 1) * 8) * 2);
        b_step = 16;
    } else {
        bph = Bh + (size_t)(tid >> 4) * Ncols + bn + (tid & 15) * 8;
        bpl = Bl + (size_t)(tid >> 4) * Ncols + bn + (tid & 15) * 8;
        b_dst = (uint32_t)(((tid >> 4) * 136 + (tid & 15) * 8) * 2);
        b_step = (size_t)16 * Ncols;
    }

    const uint32_t smb = smem_u32(&sm[0][0][0]);

    // ldmatrix offsets (bytes, within one array)
    uint32_t offa[4], offb[2];
#pragma unroll
    for (int mi = 0; mi < 4; mi++)
        offa[mi] = (uint32_t)(((wm + mi * 16 + (lane & 15)) * 24 + (lane >> 4) * 8) * 2);
#pragma unroll
    for (int nb = 0; nb < 2; nb++) {
        if (BT) offb[nb] = (uint32_t)(((wn + nb * 16 + (lane & 15)) * 24 + (lane >> 4) * 8) * 2);
        else    offb[nb] = (uint32_t)(((lane & 15) * 136 + wn + nb * 16 + (lane >> 4) * 8) * 2);
    }

    const int nk = Kdim >> 4;

    auto load_stage = [&](int st, int kc) {
        const uint32_t base = smb + (uint32_t)st * (4 * 6144);
        cp_async16(base + a_dst,             aph + (size_t)kc * 16);
        cp_async16(base + 6144 + a_dst,      apl + (size_t)kc * 16);
        cp_async16(base + 2 * 6144 + b_dst,  bph + (size_t)kc * b_step);
        cp_async16(base + 3 * 6144 + b_dst,  bpl + (size_t)kc * b_step);
        cp_commit();
    };

    load_stage(0, 0);

    for (int i = 0; i < nk; i++) {
        const int st = i & 1;
        if (i + 1 < nk) { load_stage(st ^ 1, i + 1); cp_wait<1>(); }
        else            { cp_wait<0>(); }
        __syncthreads();

        const uint32_t base = smb + (uint32_t)st * (4 * 6144);

        uint32_t fah[4][4], fal[4][4];
#pragma unroll
        for (int mi = 0; mi < 4; mi++) {
            ldsm_x4(fah[mi][0], fah[mi][1], fah[mi][2], fah[mi][3], base + offa[mi]);
            ldsm_x4(fal[mi][0], fal[mi][1], fal[mi][2], fal[mi][3], base + 6144 + offa[mi]);
        }
        uint32_t fbh[4][2], fbl[4][2];
#pragma unroll
        for (int nb = 0; nb < 2; nb++) {
            uint32_t r0, r1, r2, r3;
            if (BT) {
                ldsm_x4(r0, r1, r2, r3, base + 2 * 6144 + offb[nb]);
                fbh[2 * nb][0] = r0; fbh[2 * nb][1] = r2;
                fbh[2 * nb + 1][0] = r1; fbh[2 * nb + 1][1] = r3;
                ldsm_x4(r0, r1, r2, r3, base + 3 * 6144 + offb[nb]);
                fbl[2 * nb][0] = r0; fbl[2 * nb][1] = r2;
                fbl[2 * nb + 1][0] = r1; fbl[2 * nb + 1][1] = r3;
            } else {
                ldsm_x4_t(r0, r1, r2, r3, base + 2 * 6144 + offb[nb]);
                fbh[2 * nb][0] = r0; fbh[2 * nb][1] = r1;
                fbh[2 * nb + 1][0] = r2; fbh[2 * nb + 1][1] = r3;
                ldsm_x4_t(r0, r1, r2, r3, base + 3 * 6144 + offb[nb]);
                fbl[2 * nb][0] = r0; fbl[2 * nb][1] = r1;
                fbl[2 * nb + 1][0] = r2; fbl[2 * nb + 1][1] = r3;
            }
        }

#pragma unroll
        for (int mi = 0; mi < 4; mi++)
#pragma unroll
            for (int ni = 0; ni < 4; ni++) {
                mma16816(acc[mi][ni], fah[mi], fbh[ni]);
                mma16816(acc[mi][ni], fah[mi], fbl[ni]);
                mma16816(acc[mi][ni], fal[mi], fbh[ni]);
            }
        __syncthreads();
    }

    // epilogue
#pragma unroll
    for (int mi = 0; mi < 4; mi++) {
#pragma unroll
        for (int ni = 0; ni < 4; ni++) {
#pragma unroll
            for (int h = 0; h < 2; h++) {
                const int r = bm + wm + mi * 16 + (lane >> 2) + h * 8;
                const int c = bn + wn + ni * 8 + ((lane & 3) << 1);
                float v0 = acc[mi][ni][2 * h + 0] * alpha;
                float v1 = acc[mi][ni][2 * h + 1] * alpha;
                if (HAS_BIAS) { v0 += bias[c]; v1 += bias[c + 1]; }
                const size_t idx = (size_t)r * Ncols + c;
                if (WF32) {
                    float2 o; o.x = v0; o.y = v1;
                    *(float2*)(Cf + idx) = o;
                }
                if (WBF16) {
                    __nv_bfloat16 h0 = __float2bfloat16(v0);
                    __nv_bfloat16 h1 = __float2bfloat16(v1);
                    __nv_bfloat16 l0 = __float2bfloat16(v0 - __bfloat162float(h0));
                    __nv_bfloat16 l1 = __float2bfloat16(v1 - __bfloat162float(h1));
                    *(__nv_bfloat162*)(Ch + idx) = __halves2bfloat162(h0, h1);
                    *(__nv_bfloat162*)(Cl + idx) = __halves2bfloat162(l0, l1);
                }
            }
        }
    }
}

// ---------------------------------------------------------------------------
// Row softmax over fp32 S; emits bf16 hi/lo of the probabilities.
// ---------------------------------------------------------------------------
__global__ __launch_bounds__(256)
void softmax_split(const float* __restrict__ S, __nv_bfloat16* __restrict__ Sh,
                   __nv_bfloat16* __restrict__ Sl) {
    constexpr int T = 256;
    constexpr int VPT = N_TOK / T;  // 16
    const int row = blockIdx.x;
    const int tid = threadIdx.x;
    const float* p = S + (size_t)row * N_TOK;

    float v[VPT];
    float m = -3.0e38f;
#pragma unroll
    for (int i = 0; i < VPT; i++) {
        v[i] = p[tid + i * T];
        m = fmaxf(m, v[i]);
    }
    __shared__ float red[T];
    red[tid] = m;
    __syncthreads();
    for (int s = T / 2; s > 0; s >>= 1) {
        if (tid < s) red[tid] = fmaxf(red[tid], red[tid + s]);
        __syncthreads();
    }
    m = red[0];
    __syncthreads();

    float sum = 0.f;
#pragma unroll
    for (int i = 0; i < VPT; i++) {
        v[i] = __expf(v[i] - m);
        sum += v[i];
    }
    red[tid] = sum;
    __syncthreads();
    for (int s = T / 2; s > 0; s >>= 1) {
        if (tid < s) red[tid] += red[tid + s];
        __syncthreads();
    }
    const float inv = 1.f / red[0];
#pragma unroll
    for (int i = 0; i < VPT; i++) {
        const float w = v[i] * inv;
        const __nv_bfloat16 h = __float2bfloat16(w);
        const __nv_bfloat16 l = __float2bfloat16(w - __bfloat162float(h));
        Sh[(size_t)row * N_TOK + tid + i * T] = h;
        Sl[(size_t)row * N_TOK + tid + i * T] = l;
    }
}

// ---------------------------------------------------------------------------
// Launch
// ---------------------------------------------------------------------------
extern "C" void kernel_launch(void* const* d_in, const int* in_sizes, int n_in,
                              void* d_out, int out_size) {
    const float* x  = (const float*)d_in[0];
    const float* W1 = (const float*)d_in[1];
    const float* b1 = (const float*)d_in[2];
    const float* W2 = (const float*)d_in[3];
    const float* b2 = (const float*)d_in[4];
    const float* W3 = (const float*)d_in[5];
    const float* b3 = (const float*)d_in[6];
    float* out = (float*)d_out;

    __nv_bfloat16 *xh, *xl, *w1h, *w1l, *w2h, *w2l, *w3h, *w3l;
    __nv_bfloat16 *qh, *ql, *kh, *kl, *vh, *vl, *sh, *sl;
    float* S;
    cudaGetSymbolAddress((void**)&xh, g_xh);   cudaGetSymbolAddress((void**)&xl, g_xl);
    cudaGetSymbolAddress((void**)&w1h, g_w1h); cudaGetSymbolAddress((void**)&w1l, g_w1l);
    cudaGetSymbolAddress((void**)&w2h, g_w2h); cudaGetSymbolAddress((void**)&w2l, g_w2l);
    cudaGetSymbolAddress((void**)&w3h, g_w3h); cudaGetSymbolAddress((void**)&w3l, g_w3l);
    cudaGetSymbolAddress((void**)&qh, g_qh);   cudaGetSymbolAddress((void**)&ql, g_ql);
    cudaGetSymbolAddress((void**)&kh, g_kh);   cudaGetSymbolAddress((void**)&kl, g_kl);
    cudaGetSymbolAddress((void**)&vh, g_vh);   cudaGetSymbolAddress((void**)&vl, g_vl);
    cudaGetSymbolAddress((void**)&sh, g_sh);   cudaGetSymbolAddress((void**)&sl, g_sl);
    cudaGetSymbolAddress((void**)&S, g_S);

    const dim3 blk(256);

    // split-convert inputs
    const int nx4 = N_TOK * D_MODEL / 4;
    const int nw4 = D_MODEL * D_MODEL / 4;
    split_kernel<<<(nx4 + 255) / 256, blk>>>(x, xh, xl, nx4);
    split_kernel<<<(nw4 + 255) / 256, blk>>>(W1, w1h, w1l, nw4);
    split_kernel<<<(nw4 + 255) / 256, blk>>>(W2, w2h, w2l, nw4);
    split_kernel<<<(nw4 + 255) / 256, blk>>>(W3, w3h, w3l, nw4);

    const dim3 grid_proj(D_MODEL / 128, N_TOK / 128);  // (8, 32)
    const dim3 grid_attn(N_TOK / 128, N_TOK / 128);    // (32, 32)

    // Q/K/V projections: write bf16 hi/lo directly
    mma_gemm<true, true, false, true><<<grid_proj, blk>>>(
        xh, xl, w1h, w1l, b1, nullptr, qh, ql, N_TOK, D_MODEL, D_MODEL, 1.f);
    mma_gemm<true, true, false, true><<<grid_proj, blk>>>(
        xh, xl, w2h, w2l, b2, nullptr, kh, kl, N_TOK, D_MODEL, D_MODEL, 1.f);
    mma_gemm<true, true, false, true><<<grid_proj, blk>>>(
        xh, xl, w3h, w3l, b3, nullptr, vh, vl, N_TOK, D_MODEL, D_MODEL, 1.f);

    // S = scale * K @ Q^T  (fp32 out)
    const float scale = rsqrtf((float)D_MODEL);
    mma_gemm<true, false, true, false><<<grid_attn, blk>>>(
        kh, kl, qh, ql, nullptr, S, nullptr, nullptr, N_TOK, N_TOK, D_MODEL, scale);

    // softmax rows -> bf16 hi/lo probabilities
    softmax_split<<<N_TOK, blk>>>(S, sh, sl);

    // out = P @ V (fp32 out)
    mma_gemm<false, false, true, false><<<grid_proj, blk>>>(
        sh, sl, vh, vl, nullptr, out, nullptr, nullptr, N_TOK, D_MODEL, N_TOK, 1.f);
}

// round 5
// speedup vs baseline: 3.5628x; 1.0412x over previous
#include <cuda_runtime.h>
#include <cuda_bf16.h>
#include <cstdint>

#define N_TOK 4096
#define D_MODEL 1024

// ---------------------------------------------------------------------------
// Scratch (__device__ globals; no allocations allowed)
// ---------------------------------------------------------------------------
__device__ __nv_bfloat16 g_xh[(size_t)N_TOK * D_MODEL];
__device__ __nv_bfloat16 g_xl[(size_t)N_TOK * D_MODEL];
__device__ __nv_bfloat16 g_w1h[(size_t)D_MODEL * D_MODEL];
__device__ __nv_bfloat16 g_w1l[(size_t)D_MODEL * D_MODEL];
__device__ __nv_bfloat16 g_w2h[(size_t)D_MODEL * D_MODEL];
__device__ __nv_bfloat16 g_w2l[(size_t)D_MODEL * D_MODEL];
__device__ __nv_bfloat16 g_w3h[(size_t)D_MODEL * D_MODEL];
__device__ __nv_bfloat16 g_w3l[(size_t)D_MODEL * D_MODEL];
__device__ __nv_bfloat16 g_qh[(size_t)N_TOK * D_MODEL];
__device__ __nv_bfloat16 g_ql[(size_t)N_TOK * D_MODEL];
__device__ __nv_bfloat16 g_kh[(size_t)N_TOK * D_MODEL];
__device__ __nv_bfloat16 g_kl[(size_t)N_TOK * D_MODEL];
__device__ __nv_bfloat16 g_vh[(size_t)N_TOK * D_MODEL];
__device__ __nv_bfloat16 g_vl[(size_t)N_TOK * D_MODEL];
__device__ float         g_S [(size_t)N_TOK * N_TOK];
__device__ __nv_bfloat16 g_sh[(size_t)N_TOK * N_TOK];
__device__ __nv_bfloat16 g_sl[(size_t)N_TOK * N_TOK];

// ---------------------------------------------------------------------------
// PTX helpers
// ---------------------------------------------------------------------------
__device__ __forceinline__ uint32_t smem_u32(const void* p) {
    return (uint32_t)__cvta_generic_to_shared(p);
}
__device__ __forceinline__ void cp_async16(uint32_t dst, const void* src) {
    asm volatile("cp.async.cg.shared.global [%0], [%1], 16;\n" :: "r"(dst), "l"(src));
}
__device__ __forceinline__ void cp_commit() {
    asm volatile("cp.async.commit_group;\n" ::: "memory");
}
template <int N>
__device__ __forceinline__ void cp_wait() {
    asm volatile("cp.async.wait_group %0;\n" :: "n"(N) : "memory");
}
__device__ __forceinline__ void ldsm_x4(uint32_t& r0, uint32_t& r1, uint32_t& r2, uint32_t& r3,
                                        uint32_t addr) {
    asm volatile("ldmatrix.sync.aligned.m8n8.x4.shared.b16 {%0,%1,%2,%3}, [%4];\n"
                 : "=r"(r0), "=r"(r1), "=r"(r2), "=r"(r3) : "r"(addr));
}
__device__ __forceinline__ void ldsm_x4_t(uint32_t& r0, uint32_t& r1, uint32_t& r2, uint32_t& r3,
                                          uint32_t addr) {
    asm volatile("ldmatrix.sync.aligned.m8n8.x4.trans.shared.b16 {%0,%1,%2,%3}, [%4];\n"
                 : "=r"(r0), "=r"(r1), "=r"(r2), "=r"(r3) : "r"(addr));
}
__device__ __forceinline__ void mma16816(float* c, const uint32_t* a, const uint32_t* b) {
    asm volatile(
        "mma.sync.aligned.m16n8k16.row.col.f32.bf16.bf16.f32 "
        "{%0,%1,%2,%3}, {%4,%5,%6,%7}, {%8,%9}, {%0,%1,%2,%3};\n"
        : "+f"(c[0]), "+f"(c[1]), "+f"(c[2]), "+f"(c[3])
        : "r"(a[0]), "r"(a[1]), "r"(a[2]), "r"(a[3]), "r"(b[0]), "r"(b[1]));
}

// ---------------------------------------------------------------------------
// Split fp32 -> (hi, lo) bf16
// ---------------------------------------------------------------------------
__device__ __forceinline__ void split_body(const float* __restrict__ in,
                                           __nv_bfloat16* __restrict__ hi,
                                           __nv_bfloat16* __restrict__ lo, int i, int n4) {
    if (i >= n4) return;
    float4 v = ((const float4*)in)[i];
    __nv_bfloat16 h0 = __float2bfloat16(v.x);
    __nv_bfloat16 h1 = __float2bfloat16(v.y);
    __nv_bfloat16 h2 = __float2bfloat16(v.z);
    __nv_bfloat16 h3 = __float2bfloat16(v.w);
    __nv_bfloat16 l0 = __float2bfloat16(v.x - __bfloat162float(h0));
    __nv_bfloat16 l1 = __float2bfloat16(v.y - __bfloat162float(h1));
    __nv_bfloat16 l2 = __float2bfloat16(v.z - __bfloat162float(h2));
    __nv_bfloat16 l3 = __float2bfloat16(v.w - __bfloat162float(h3));
    ((__nv_bfloat162*)hi)[2 * i + 0] = __halves2bfloat162(h0, h1);
    ((__nv_bfloat162*)hi)[2 * i + 1] = __halves2bfloat162(h2, h3);
    ((__nv_bfloat162*)lo)[2 * i + 0] = __halves2bfloat162(l0, l1);
    ((__nv_bfloat162*)lo)[2 * i + 1] = __halves2bfloat162(l2, l3);
}

__global__ __launch_bounds__(256)
void split_kernel(const float* __restrict__ in, __nv_bfloat16* __restrict__ hi,
                  __nv_bfloat16* __restrict__ lo, int n4) {
    split_body(in, hi, lo, blockIdx.x * blockDim.x + threadIdx.x, n4);
}

// batched split for the three weight matrices (same size)
__global__ __launch_bounds__(256)
void split3_kernel(const float* __restrict__ i0, __nv_bfloat16* __restrict__ h0, __nv_bfloat16* __restrict__ l0,
                   const float* __restrict__ i1, __nv_bfloat16* __restrict__ h1, __nv_bfloat16* __restrict__ l1,
                   const float* __restrict__ i2, __nv_bfloat16* __restrict__ h2, __nv_bfloat16* __restrict__ l2,
                   int n4) {
    const int i = blockIdx.x * blockDim.x + threadIdx.x;
    if (blockIdx.y == 0)      split_body(i0, h0, l0, i, n4);
    else if (blockIdx.y == 1) split_body(i1, h1, l1, i, n4);
    else                      split_body(i2, h2, l2, i, n4);
}

// ---------------------------------------------------------------------------
// Split-bf16 tensor-core GEMM (mma.sync).
//   C[M,Ncols] = alpha * A @ op(B) (+ bias)
//   BT=true : B hi/lo is [Ncols,Kdim] row-major (A @ B^T)
//   BT=false: B hi/lo is [Kdim,Ncols] row-major (A @ B)
// Block 128x128, 8 warps (warp tile 64x32), BK=16.
// 3-stage cp.async pipeline, ONE __syncthreads per chunk, 2 CTAs/SM.
// ---------------------------------------------------------------------------
#define ST_BYTES 24576   // per stage: 4 arrays x 3072 halves (6144 B)
#define GM_SMEM  (3 * ST_BYTES)

template <bool BT, bool HAS_BIAS, bool WF32, bool WBF16>
__global__ __launch_bounds__(256, 2)
void mma_gemm(const __nv_bfloat16* __restrict__ Ah, const __nv_bfloat16* __restrict__ Al,
              const __nv_bfloat16* __restrict__ Bh, const __nv_bfloat16* __restrict__ Bl,
              const float* __restrict__ bias, float* __restrict__ Cf,
              __nv_bfloat16* __restrict__ Ch, __nv_bfloat16* __restrict__ Cl,
              int M, int Ncols, int Kdim, float alpha) {
    extern __shared__ __nv_bfloat16 sm[];   // [3][4][3072]

    const int tid  = threadIdx.x;
    const int lane = tid & 31;
    const int wid  = tid >> 5;
    const int wm   = (wid >> 2) * 64;
    const int wn   = (wid & 3) * 32;
    const int bm   = blockIdx.y * 128;
    const int bn   = blockIdx.x * 128;

    float acc[4][4][4];
#pragma unroll
    for (int i = 0; i < 4; i++)
#pragma unroll
        for (int j = 0; j < 4; j++)
#pragma unroll
            for (int k = 0; k < 4; k++) acc[i][j][k] = 0.f;

    // gmem load assignments (one 16B cp.async per thread per array per chunk)
    const __nv_bfloat16* aph = Ah + (size_t)(bm + (tid >> 1)) * Kdim + (tid & 1) * 8;
    const __nv_bfloat16* apl = Al + (size_t)(bm + (tid >> 1)) * Kdim + (tid & 1) * 8;
    const uint32_t a_dst = (uint32_t)(((tid >> 1) * 24 + (tid & 1) * 8) * 2);

    const __nv_bfloat16 *bph, *bpl;
    uint32_t b_dst;
    size_t b_step;
    if (BT) {
        bph = Bh + (size_t)(bn + (tid >> 1)) * Kdim + (tid & 1) * 8;
        bpl = Bl + (size_t)(bn + (tid >> 1)) * Kdim + (tid & 1) * 8;
        b_dst = (uint32_t)(((tid >> 1) * 24 + (tid & 1) * 8) * 2);
        b_step = 16;
    } else {
        bph = Bh + (size_t)(tid >> 4) * Ncols + bn + (tid & 15) * 8;
        bpl = Bl + (size_t)(tid >> 4) * Ncols + bn + (tid & 15) * 8;
        b_dst = (uint32_t)(((tid >> 4) * 136 + (tid & 15) * 8) * 2);
        b_step = (size_t)16 * Ncols;
    }

    const uint32_t smb = smem_u32(&sm[0]);

    uint32_t offa[4], offb[2];
#pragma unroll
    for (int mi = 0; mi < 4; mi++)
        offa[mi] = (uint32_t)(((wm + mi * 16 + (lane & 15)) * 24 + (lane >> 4) * 8) * 2);
#pragma unroll
    for (int nb = 0; nb < 2; nb++) {
        if (BT) offb[nb] = (uint32_t)(((wn + nb * 16 + (lane & 15)) * 24 + (lane >> 4) * 8) * 2);
        else    offb[nb] = (uint32_t)(((lane & 15) * 136 + wn + nb * 16 + (lane >> 4) * 8) * 2);
    }

    const int nk = Kdim >> 4;

    auto load_stage = [&](int st, int kc) {
        const uint32_t base = smb + (uint32_t)st * ST_BYTES;
        cp_async16(base + a_dst,            aph + (size_t)kc * 16);
        cp_async16(base + 6144 + a_dst,     apl + (size_t)kc * 16);
        cp_async16(base + 2 * 6144 + b_dst, bph + (size_t)kc * b_step);
        cp_async16(base + 3 * 6144 + b_dst, bpl + (size_t)kc * b_step);
        cp_commit();
    };

    // prologue: stages 0 and 1
    load_stage(0, 0);
    if (nk > 1) load_stage(1, 1);

    for (int i = 0; i < nk; i++) {
        const int st = i % 3;
        // 1) my groups: need stage i complete (newest outstanding: stage i+1 if issued)
        if (i + 1 < nk) cp_wait<1>();
        else            cp_wait<0>();
        // 2) all threads' stage-i data visible; all warps done with slot (i+2)%3 (= stage i-1)
        __syncthreads();
        // 3) refill the freed slot
        if (i + 2 < nk) load_stage((i + 2) % 3, i + 2);
        // 4) compute stage i
        const uint32_t base = smb + (uint32_t)st * ST_BYTES;

        uint32_t fah[4][4], fal[4][4];
#pragma unroll
        for (int mi = 0; mi < 4; mi++) {
            ldsm_x4(fah[mi][0], fah[mi][1], fah[mi][2], fah[mi][3], base + offa[mi]);
            ldsm_x4(fal[mi][0], fal[mi][1], fal[mi][2], fal[mi][3], base + 6144 + offa[mi]);
        }
        uint32_t fbh[4][2], fbl[4][2];
#pragma unroll
        for (int nb = 0; nb < 2; nb++) {
            uint32_t r0, r1, r2, r3;
            if (BT) {
                ldsm_x4(r0, r1, r2, r3, base + 2 * 6144 + offb[nb]);
                fbh[2 * nb][0] = r0; fbh[2 * nb][1] = r2;
                fbh[2 * nb + 1][0] = r1; fbh[2 * nb + 1][1] = r3;
                ldsm_x4(r0, r1, r2, r3, base + 3 * 6144 + offb[nb]);
                fbl[2 * nb][0] = r0; fbl[2 * nb][1] = r2;
                fbl[2 * nb + 1][0] = r1; fbl[2 * nb + 1][1] = r3;
            } else {
                ldsm_x4_t(r0, r1, r2, r3, base + 2 * 6144 + offb[nb]);
                fbh[2 * nb][0] = r0; fbh[2 * nb][1] = r1;
                fbh[2 * nb + 1][0] = r2; fbh[2 * nb + 1][1] = r3;
                ldsm_x4_t(r0, r1, r2, r3, base + 3 * 6144 + offb[nb]);
                fbl[2 * nb][0] = r0; fbl[2 * nb][1] = r1;
                fbl[2 * nb + 1][0] = r2; fbl[2 * nb + 1][1] = r3;
            }
        }

#pragma unroll
        for (int mi = 0; mi < 4; mi++)
#pragma unroll
            for (int ni = 0; ni < 4; ni++) {
                mma16816(acc[mi][ni], fah[mi], fbh[ni]);
                mma16816(acc[mi][ni], fah[mi], fbl[ni]);
                mma16816(acc[mi][ni], fal[mi], fbh[ni]);
            }
        // no trailing barrier: next iteration's barrier protects slot reuse
    }

    // epilogue
#pragma unroll
    for (int mi = 0; mi < 4; mi++) {
#pragma unroll
        for (int ni = 0; ni < 4; ni++) {
#pragma unroll
            for (int h = 0; h < 2; h++) {
                const int r = bm + wm + mi * 16 + (lane >> 2) + h * 8;
                const int c = bn + wn + ni * 8 + ((lane & 3) << 1);
                float v0 = acc[mi][ni][2 * h + 0] * alpha;
                float v1 = acc[mi][ni][2 * h + 1] * alpha;
                if (HAS_BIAS) { v0 += bias[c]; v1 += bias[c + 1]; }
                const size_t idx = (size_t)r * Ncols + c;
                if (WF32) {
                    float2 o; o.x = v0; o.y = v1;
                    *(float2*)(Cf + idx) = o;
                }
                if (WBF16) {
                    __nv_bfloat16 h0 = __float2bfloat16(v0);
                    __nv_bfloat16 h1 = __float2bfloat16(v1);
                    __nv_bfloat16 l0 = __float2bfloat16(v0 - __bfloat162float(h0));
                    __nv_bfloat16 l1 = __float2bfloat16(v1 - __bfloat162float(h1));
                    *(__nv_bfloat162*)(Ch + idx) = __halves2bfloat162(h0, h1);
                    *(__nv_bfloat162*)(Cl + idx) = __halves2bfloat162(l0, l1);
                }
            }
        }
    }
}

// ---------------------------------------------------------------------------
// Row softmax over fp32 S; emits bf16 hi/lo of the probabilities.
// ---------------------------------------------------------------------------
__global__ __launch_bounds__(256)
void softmax_split(const float* __restrict__ S, __nv_bfloat16* __restrict__ Sh,
                   __nv_bfloat16* __restrict__ Sl) {
    constexpr int T = 256;
    constexpr int VPT = N_TOK / T;  // 16
    const int row = blockIdx.x;
    const int tid = threadIdx.x;
    const float* p = S + (size_t)row * N_TOK;

    float v[VPT];
    float m = -3.0e38f;
#pragma unroll
    for (int i = 0; i < VPT; i++) {
        v[i] = p[tid + i * T];
        m = fmaxf(m, v[i]);
    }
    __shared__ float red[T];
    red[tid] = m;
    __syncthreads();
    for (int s = T / 2; s > 0; s >>= 1) {
        if (tid < s) red[tid] = fmaxf(red[tid], red[tid + s]);
        __syncthreads();
    }
    m = red[0];
    __syncthreads();

    float sum = 0.f;
#pragma unroll
    for (int i = 0; i < VPT; i++) {
        v[i] = __expf(v[i] - m);
        sum += v[i];
    }
    red[tid] = sum;
    __syncthreads();
    for (int s = T / 2; s > 0; s >>= 1) {
        if (tid < s) red[tid] += red[tid + s];
        __syncthreads();
    }
    const float inv = 1.f / red[0];
#pragma unroll
    for (int i = 0; i < VPT; i++) {
        const float w = v[i] * inv;
        const __nv_bfloat16 h = __float2bfloat16(w);
        const __nv_bfloat16 l = __float2bfloat16(w - __bfloat162float(h));
        Sh[(size_t)row * N_TOK + tid + i * T] = h;
        Sl[(size_t)row * N_TOK + tid + i * T] = l;
    }
}

// ---------------------------------------------------------------------------
// Launch
// ---------------------------------------------------------------------------
extern "C" void kernel_launch(void* const* d_in, const int* in_sizes, int n_in,
                              void* d_out, int out_size) {
    const float* x  = (const float*)d_in[0];
    const float* W1 = (const float*)d_in[1];
    const float* b1 = (const float*)d_in[2];
    const float* W2 = (const float*)d_in[3];
    const float* b2 = (const float*)d_in[4];
    const float* W3 = (const float*)d_in[5];
    const float* b3 = (const float*)d_in[6];
    float* out = (float*)d_out;

    __nv_bfloat16 *xh, *xl, *w1h, *w1l, *w2h, *w2l, *w3h, *w3l;
    __nv_bfloat16 *qh, *ql, *kh, *kl, *vh, *vl, *sh, *sl;
    float* S;
    cudaGetSymbolAddress((void**)&xh, g_xh);   cudaGetSymbolAddress((void**)&xl, g_xl);
    cudaGetSymbolAddress((void**)&w1h, g_w1h); cudaGetSymbolAddress((void**)&w1l, g_w1l);
    cudaGetSymbolAddress((void**)&w2h, g_w2h); cudaGetSymbolAddress((void**)&w2l, g_w2l);
    cudaGetSymbolAddress((void**)&w3h, g_w3h); cudaGetSymbolAddress((void**)&w3l, g_w3l);
    cudaGetSymbolAddress((void**)&qh, g_qh);   cudaGetSymbolAddress((void**)&ql, g_ql);
    cudaGetSymbolAddress((void**)&kh, g_kh);   cudaGetSymbolAddress((void**)&kl, g_kl);
    cudaGetSymbolAddress((void**)&vh, g_vh);   cudaGetSymbolAddress((void**)&vl, g_vl);
    cudaGetSymbolAddress((void**)&sh, g_sh);   cudaGetSymbolAddress((void**)&sl, g_sl);
    cudaGetSymbolAddress((void**)&S, g_S);

    cudaFuncSetAttribute(mma_gemm<true, true, false, true>,
                         cudaFuncAttributeMaxDynamicSharedMemorySize, GM_SMEM);
    cudaFuncSetAttribute(mma_gemm<true, false, true, false>,
                         cudaFuncAttributeMaxDynamicSharedMemorySize, GM_SMEM);
    cudaFuncSetAttribute(mma_gemm<false, false, true, false>,
                         cudaFuncAttributeMaxDynamicSharedMemorySize, GM_SMEM);

    const dim3 blk(256);

    // split-convert inputs
    const int nx4 = N_TOK * D_MODEL / 4;
    const int nw4 = D_MODEL * D_MODEL / 4;
    split_kernel<<<(nx4 + 255) / 256, blk>>>(x, xh, xl, nx4);
    split3_kernel<<<dim3((nw4 + 255) / 256, 3), blk>>>(
        W1, w1h, w1l, W2, w2h, w2l, W3, w3h, w3l, nw4);

    const dim3 grid_proj(D_MODEL / 128, N_TOK / 128);  // (8, 32)
    const dim3 grid_attn(N_TOK / 128, N_TOK / 128);    // (32, 32)

    // Q/K/V projections: write bf16 hi/lo directly
    mma_gemm<true, true, false, true><<<grid_proj, blk, GM_SMEM>>>(
        xh, xl, w1h, w1l, b1, nullptr, qh, ql, N_TOK, D_MODEL, D_MODEL, 1.f);
    mma_gemm<true, true, false, true><<<grid_proj, blk, GM_SMEM>>>(
        xh, xl, w2h, w2l, b2, nullptr, kh, kl, N_TOK, D_MODEL, D_MODEL, 1.f);
    mma_gemm<true, true, false, true><<<grid_proj, blk, GM_SMEM>>>(
        xh, xl, w3h, w3l, b3, nullptr, vh, vl, N_TOK, D_MODEL, D_MODEL, 1.f);

    // S = scale * K @ Q^T  (fp32 out)
    const float scale = rsqrtf((float)D_MODEL);
    mma_gemm<true, false, true, false><<<grid_attn, blk, GM_SMEM>>>(
        kh, kl, qh, ql, nullptr, S, nullptr, nullptr, N_TOK, N_TOK, D_MODEL, scale);

    // softmax rows -> bf16 hi/lo probabilities
    softmax_split<<<N_TOK, blk>>>(S, sh, sl);

    // out = P @ V (fp32 out)
    mma_gemm<false, false, true, false><<<grid_proj, blk, GM_SMEM>>>(
        sh, sl, vh, vl, nullptr, out, nullptr, nullptr, N_TOK, D_MODEL, N_TOK, 1.f);
}

// round 7
// speedup vs baseline: 4.0234x; 1.1293x over previous
#include <cuda_runtime.h>
#include <cuda_bf16.h>
#include <cstdint>

#define N_TOK 4096
#define D_MODEL 1024

// ---------------------------------------------------------------------------
// Scratch (__device__ globals; no allocations allowed)
// ---------------------------------------------------------------------------
__device__ __nv_bfloat16 g_xh[(size_t)N_TOK * D_MODEL];
__device__ __nv_bfloat16 g_xl[(size_t)N_TOK * D_MODEL];
__device__ __nv_bfloat16 g_w1h[(size_t)D_MODEL * D_MODEL];
__device__ __nv_bfloat16 g_w1l[(size_t)D_MODEL * D_MODEL];
__device__ __nv_bfloat16 g_w2h[(size_t)D_MODEL * D_MODEL];
__device__ __nv_bfloat16 g_w2l[(size_t)D_MODEL * D_MODEL];
__device__ __nv_bfloat16 g_w3h[(size_t)D_MODEL * D_MODEL];
__device__ __nv_bfloat16 g_w3l[(size_t)D_MODEL * D_MODEL];
__device__ __nv_bfloat16 g_qh[(size_t)N_TOK * D_MODEL];
__device__ __nv_bfloat16 g_ql[(size_t)N_TOK * D_MODEL];
__device__ __nv_bfloat16 g_kh[(size_t)N_TOK * D_MODEL];
__device__ __nv_bfloat16 g_kl[(size_t)N_TOK * D_MODEL];
__device__ __nv_bfloat16 g_vh[(size_t)N_TOK * D_MODEL];
__device__ __nv_bfloat16 g_vl[(size_t)N_TOK * D_MODEL];
__device__ float         g_S [(size_t)N_TOK * N_TOK];
__device__ __nv_bfloat16 g_sh[(size_t)N_TOK * N_TOK];
__device__ __nv_bfloat16 g_sl[(size_t)N_TOK * N_TOK];

// ---------------------------------------------------------------------------
// PTX helpers
// ---------------------------------------------------------------------------
__device__ __forceinline__ uint32_t smem_u32(const void* p) {
    return (uint32_t)__cvta_generic_to_shared(p);
}
__device__ __forceinline__ void cp_async16(uint32_t dst, const void* src) {
    asm volatile("cp.async.cg.shared.global [%0], [%1], 16;\n" :: "r"(dst), "l"(src));
}
__device__ __forceinline__ void cp_commit() {
    asm volatile("cp.async.commit_group;\n" ::: "memory");
}
template <int N>
__device__ __forceinline__ void cp_wait() {
    asm volatile("cp.async.wait_group %0;\n" :: "n"(N) : "memory");
}
__device__ __forceinline__ void ldsm_x4(uint32_t& r0, uint32_t& r1, uint32_t& r2, uint32_t& r3,
                                        uint32_t addr) {
    asm volatile("ldmatrix.sync.aligned.m8n8.x4.shared.b16 {%0,%1,%2,%3}, [%4];\n"
                 : "=r"(r0), "=r"(r1), "=r"(r2), "=r"(r3) : "r"(addr));
}
__device__ __forceinline__ void ldsm_x4_t(uint32_t& r0, uint32_t& r1, uint32_t& r2, uint32_t& r3,
                                          uint32_t addr) {
    asm volatile("ldmatrix.sync.aligned.m8n8.x4.trans.shared.b16 {%0,%1,%2,%3}, [%4];\n"
                 : "=r"(r0), "=r"(r1), "=r"(r2), "=r"(r3) : "r"(addr));
}
__device__ __forceinline__ void mma16816(float* c, const uint32_t* a, const uint32_t* b) {
    asm volatile(
        "mma.sync.aligned.m16n8k16.row.col.f32.bf16.bf16.f32 "
        "{%0,%1,%2,%3}, {%4,%5,%6,%7}, {%8,%9}, {%0,%1,%2,%3};\n"
        : "+f"(c[0]), "+f"(c[1]), "+f"(c[2]), "+f"(c[3])
        : "r"(a[0]), "r"(a[1]), "r"(a[2]), "r"(a[3]), "r"(b[0]), "r"(b[1]));
}

// ---------------------------------------------------------------------------
// Split fp32 -> (hi, lo) bf16
// ---------------------------------------------------------------------------
__device__ __forceinline__ void split_body(const float* __restrict__ in,
                                           __nv_bfloat16* __restrict__ hi,
                                           __nv_bfloat16* __restrict__ lo, int i, int n4) {
    if (i >= n4) return;
    float4 v = ((const float4*)in)[i];
    __nv_bfloat16 h0 = __float2bfloat16(v.x);
    __nv_bfloat16 h1 = __float2bfloat16(v.y);
    __nv_bfloat16 h2 = __float2bfloat16(v.z);
    __nv_bfloat16 h3 = __float2bfloat16(v.w);
    __nv_bfloat16 l0 = __float2bfloat16(v.x - __bfloat162float(h0));
    __nv_bfloat16 l1 = __float2bfloat16(v.y - __bfloat162float(h1));
    __nv_bfloat16 l2 = __float2bfloat16(v.z - __bfloat162float(h2));
    __nv_bfloat16 l3 = __float2bfloat16(v.w - __bfloat162float(h3));
    ((__nv_bfloat162*)hi)[2 * i + 0] = __halves2bfloat162(h0, h1);
    ((__nv_bfloat162*)hi)[2 * i + 1] = __halves2bfloat162(h2, h3);
    ((__nv_bfloat162*)lo)[2 * i + 0] = __halves2bfloat162(l0, l1);
    ((__nv_bfloat162*)lo)[2 * i + 1] = __halves2bfloat162(l2, l3);
}

__global__ __launch_bounds__(256)
void split_kernel(const float* __restrict__ in, __nv_bfloat16* __restrict__ hi,
                  __nv_bfloat16* __restrict__ lo, int n4) {
    split_body(in, hi, lo, blockIdx.x * blockDim.x + threadIdx.x, n4);
}

__global__ __launch_bounds__(256)
void split3_kernel(const float* __restrict__ i0, __nv_bfloat16* __restrict__ h0, __nv_bfloat16* __restrict__ l0,
                   const float* __restrict__ i1, __nv_bfloat16* __restrict__ h1, __nv_bfloat16* __restrict__ l1,
                   const float* __restrict__ i2, __nv_bfloat16* __restrict__ h2, __nv_bfloat16* __restrict__ l2,
                   int n4) {
    const int i = blockIdx.x * blockDim.x + threadIdx.x;
    if (blockIdx.y == 0)      split_body(i0, h0, l0, i, n4);
    else if (blockIdx.y == 1) split_body(i1, h1, l1, i, n4);
    else                      split_body(i2, h2, l2, i, n4);
}

// ---------------------------------------------------------------------------
// Split-bf16 tensor-core GEMM (mma.sync).  BK=32, 3-stage cp.async pipeline,
// one __syncthreads per 32-wide K chunk, 2 CTAs/SM.
//   BT=true : B hi/lo is [Ncols,Kdim] row-major (A @ B^T)
//   BT=false: B hi/lo is [Kdim,Ncols] row-major (A @ B)
// Block 128x128, 8 warps (warp tile 64x32).
// K-major smem arrays: 128 rows x 64B (4 granules of 16B), XOR-swizzled:
//   phys granule g' = g ^ ((row>>1)&3)  -> 16B aligned, ldsm conflict-free.
// B [K][N] (trans) array: 32 rows x 272B pitch (unchanged, proven).
// ---------------------------------------------------------------------------
#define ARR_KMAJ 8192                     // 128 * 64
#define BSZ_TRUE 8192
#define BSZ_FALSE 8704                    // 32 * 272
#define ST_BYTES(BT_) (2 * ARR_KMAJ + 2 * ((BT_) ? BSZ_TRUE : BSZ_FALSE))
#define GM_SMEM(BT_)  (3 * ST_BYTES(BT_))

template <bool BT, bool HAS_BIAS, bool WF32, bool WBF16, bool QKV3>
__global__ __launch_bounds__(256, 2)
void mma_gemm(const __nv_bfloat16* __restrict__ Ah, const __nv_bfloat16* __restrict__ Al,
              const __nv_bfloat16* __restrict__ Bh0, const __nv_bfloat16* __restrict__ Bl0,
              const __nv_bfloat16* __restrict__ Bh1, const __nv_bfloat16* __restrict__ Bl1,
              const __nv_bfloat16* __restrict__ Bh2, const __nv_bfloat16* __restrict__ Bl2,
              const float* __restrict__ bias0, const float* __restrict__ bias1,
              const float* __restrict__ bias2,
              float* __restrict__ Cf,
              __nv_bfloat16* __restrict__ Ch0, __nv_bfloat16* __restrict__ Cl0,
              __nv_bfloat16* __restrict__ Ch1, __nv_bfloat16* __restrict__ Cl1,
              __nv_bfloat16* __restrict__ Ch2, __nv_bfloat16* __restrict__ Cl2,
              int M, int Ncols, int Kdim, float alpha) {
    extern __shared__ __nv_bfloat16 sm[];

    constexpr int BSZ = BT ? BSZ_TRUE : BSZ_FALSE;
    constexpr int STB = 2 * ARR_KMAJ + 2 * BSZ;
    constexpr uint32_t OFF_AL = ARR_KMAJ;
    constexpr uint32_t OFF_BH = 2 * ARR_KMAJ;
    constexpr uint32_t OFF_BL = 2 * ARR_KMAJ + BSZ;

    const int tid  = threadIdx.x;
    const int lane = tid & 31;
    const int wid  = tid >> 5;
    const int wm   = (wid >> 2) * 64;
    const int wn   = (wid & 3) * 32;
    const int bm   = blockIdx.y * 128;
    const int bn   = blockIdx.x * 128;

    const __nv_bfloat16* Bh = Bh0;
    const __nv_bfloat16* Bl = Bl0;
    const float* bias = bias0;
    __nv_bfloat16* Ch = Ch0;
    __nv_bfloat16* Cl = Cl0;
    if (QKV3) {
        if (blockIdx.z == 1) { Bh = Bh1; Bl = Bl1; bias = bias1; Ch = Ch1; Cl = Cl1; }
        else if (blockIdx.z == 2) { Bh = Bh2; Bl = Bl2; bias = bias2; Ch = Ch2; Cl = Cl2; }
    }

    float acc[4][4][4];
#pragma unroll
    for (int i = 0; i < 4; i++)
#pragma unroll
        for (int j = 0; j < 4; j++)
#pragma unroll
            for (int k = 0; k < 4; k++) acc[i][j][k] = 0.f;

    const uint32_t smb = smem_u32(&sm[0]);

    // ldsm row bases + swizzle masks (K-major arrays)
    uint32_t rowa[4], swza[4];
#pragma unroll
    for (int mi = 0; mi < 4; mi++) {
        const int r = wm + mi * 16 + (lane & 15);
        rowa[mi] = (uint32_t)(r * 64);
        swza[mi] = (uint32_t)((r >> 1) & 3);
    }
    uint32_t rowb[2], swzb[2], offbt[2];
#pragma unroll
    for (int nb = 0; nb < 2; nb++) {
        if (BT) {
            const int r = wn + nb * 16 + (lane & 15);
            rowb[nb] = (uint32_t)(r * 64);
            swzb[nb] = (uint32_t)((r >> 1) & 3);
        } else {
            offbt[nb] = (uint32_t)((lane & 15) * 272 + (wn + nb * 16 + (lane >> 4) * 8) * 2);
        }
    }

    const int nk = Kdim >> 5;   // BK=32 chunks

    auto load_stage = [&](int st, int kc) {
        const uint32_t base = smb + (uint32_t)st * STB;
        const int k0 = kc * 32;
#pragma unroll
        for (int p = 0; p < 2; p++) {
            const int G = tid * 2 + p;
            {   // A hi/lo: K-major, 64B rows, swizzled granules
                const int r = G >> 2, g = G & 3;
                const uint32_t d = (uint32_t)(r * 64 + ((g ^ ((r >> 1) & 3)) * 16));
                const size_t o = (size_t)(bm + r) * Kdim + k0 + g * 8;
                cp_async16(base + d, Ah + o);
                cp_async16(base + OFF_AL + d, Al + o);
            }
            if (BT) {
                const int r = G >> 2, g = G & 3;
                const uint32_t d = (uint32_t)(r * 64 + ((g ^ ((r >> 1) & 3)) * 16));
                const size_t o = (size_t)(bn + r) * Kdim + k0 + g * 8;
                cp_async16(base + OFF_BH + d, Bh + o);
                cp_async16(base + OFF_BL + d, Bl + o);
            } else {
                const int r = G >> 4, c = G & 15;
                const uint32_t d = (uint32_t)(r * 272 + c * 16);
                const size_t o = (size_t)(k0 + r) * Ncols + bn + c * 8;
                cp_async16(base + OFF_BH + d, Bh + o);
                cp_async16(base + OFF_BL + d, Bl + o);
            }
        }
        cp_commit();
    };

    load_stage(0, 0);
    if (nk > 1) load_stage(1, 1);

    for (int i = 0; i < nk; i++) {
        const int st = i % 3;
        if (i + 1 < nk) cp_wait<1>();
        else            cp_wait<0>();
        __syncthreads();
        if (i + 2 < nk) load_stage((i + 2) % 3, i + 2);

        const uint32_t base = smb + (uint32_t)st * STB;

#pragma unroll
        for (int ks = 0; ks < 2; ks++) {
            const uint32_t gbase = (uint32_t)(ks * 2 + (lane >> 4));  // logical granule 0..3

            uint32_t fah[4][4], fal[4][4];
#pragma unroll
            for (int mi = 0; mi < 4; mi++) {
                const uint32_t d = rowa[mi] + ((gbase ^ swza[mi]) * 16);
                ldsm_x4(fah[mi][0], fah[mi][1], fah[mi][2], fah[mi][3], base + d);
                ldsm_x4(fal[mi][0], fal[mi][1], fal[mi][2], fal[mi][3], base + OFF_AL + d);
            }
            uint32_t fbh[4][2], fbl[4][2];
#pragma unroll
            for (int nb = 0; nb < 2; nb++) {
                uint32_t r0, r1, r2, r3;
                if (BT) {
                    const uint32_t d = rowb[nb] + ((gbase ^ swzb[nb]) * 16);
                    ldsm_x4(r0, r1, r2, r3, base + OFF_BH + d);
                    fbh[2 * nb][0] = r0; fbh[2 * nb][1] = r2;
                    fbh[2 * nb + 1][0] = r1; fbh[2 * nb + 1][1] = r3;
                    ldsm_x4(r0, r1, r2, r3, base + OFF_BL + d);
                    fbl[2 * nb][0] = r0; fbl[2 * nb][1] = r2;
                    fbl[2 * nb + 1][0] = r1; fbl[2 * nb + 1][1] = r3;
                } else {
                    const uint32_t d = offbt[nb] + (uint32_t)(ks * 16 * 272);
                    ldsm_x4_t(r0, r1, r2, r3, base + OFF_BH + d);
                    fbh[2 * nb][0] = r0; fbh[2 * nb][1] = r1;
                    fbh[2 * nb + 1][0] = r2; fbh[2 * nb + 1][1] = r3;
                    ldsm_x4_t(r0, r1, r2, r3, base + OFF_BL + d);
                    fbl[2 * nb][0] = r0; fbl[2 * nb][1] = r1;
                    fbl[2 * nb + 1][0] = r2; fbl[2 * nb + 1][1] = r3;
                }
            }

#pragma unroll
            for (int mi = 0; mi < 4; mi++)
#pragma unroll
                for (int ni = 0; ni < 4; ni++) {
                    mma16816(acc[mi][ni], fah[mi], fbh[ni]);
                    mma16816(acc[mi][ni], fah[mi], fbl[ni]);
                    mma16816(acc[mi][ni], fal[mi], fbh[ni]);
                }
        }
    }

    // ---- epilogue
#pragma unroll
    for (int mi = 0; mi < 4; mi++) {
#pragma unroll
        for (int ni = 0; ni < 4; ni++) {
#pragma unroll
            for (int h = 0; h < 2; h++) {
                const int r = bm + wm + mi * 16 + (lane >> 2) + h * 8;
                const int c = bn + wn + ni * 8 + ((lane & 3) << 1);
                float v0 = acc[mi][ni][2 * h + 0] * alpha;
                float v1 = acc[mi][ni][2 * h + 1] * alpha;
                if (HAS_BIAS) { v0 += bias[c]; v1 += bias[c + 1]; }
                const size_t idx = (size_t)r * Ncols + c;
                if (WF32) {
                    float2 o; o.x = v0; o.y = v1;
                    *(float2*)(Cf + idx) = o;
                }
                if (WBF16) {
                    __nv_bfloat16 h0 = __float2bfloat16(v0);
                    __nv_bfloat16 h1 = __float2bfloat16(v1);
                    __nv_bfloat16 l0 = __float2bfloat16(v0 - __bfloat162float(h0));
                    __nv_bfloat16 l1 = __float2bfloat16(v1 - __bfloat162float(h1));
                    *(__nv_bfloat162*)(Ch + idx) = __halves2bfloat162(h0, h1);
                    *(__nv_bfloat162*)(Cl + idx) = __halves2bfloat162(l0, l1);
                }
            }
        }
    }
}

// ---------------------------------------------------------------------------
// Row softmax over fp32 S; emits bf16 hi/lo of the probabilities.
// ---------------------------------------------------------------------------
__global__ __launch_bounds__(256)
void softmax_split(const float* __restrict__ S, __nv_bfloat16* __restrict__ Sh,
                   __nv_bfloat16* __restrict__ Sl) {
    constexpr int T = 256;
    constexpr int VPT = N_TOK / T;  // 16
    const int row = blockIdx.x;
    const int tid = threadIdx.x;
    const float* p = S + (size_t)row * N_TOK;

    float v[VPT];
    float m = -3.0e38f;
#pragma unroll
    for (int i = 0; i < VPT; i++) {
        v[i] = p[tid + i * T];
        m = fmaxf(m, v[i]);
    }
    __shared__ float red[T];
    red[tid] = m;
    __syncthreads();
    for (int s = T / 2; s > 0; s >>= 1) {
        if (tid < s) red[tid] = fmaxf(red[tid], red[tid + s]);
        __syncthreads();
    }
    m = red[0];
    __syncthreads();

    float sum = 0.f;
#pragma unroll
    for (int i = 0; i < VPT; i++) {
        v[i] = __expf(v[i] - m);
        sum += v[i];
    }
    red[tid] = sum;
    __syncthreads();
    for (int s = T / 2; s > 0; s >>= 1) {
        if (tid < s) red[tid] += red[tid + s];
        __syncthreads();
    }
    const float inv = 1.f / red[0];
#pragma unroll
    for (int i = 0; i < VPT; i++) {
        const float w = v[i] * inv;
        const __nv_bfloat16 h = __float2bfloat16(w);
        const __nv_bfloat16 l = __float2bfloat16(w - __bfloat162float(h));
        Sh[(size_t)row * N_TOK + tid + i * T] = h;
        Sl[(size_t)row * N_TOK + tid + i * T] = l;
    }
}

// ---------------------------------------------------------------------------
// Launch
// ---------------------------------------------------------------------------
extern "C" void kernel_launch(void* const* d_in, const int* in_sizes, int n_in,
                              void* d_out, int out_size) {
    const float* x  = (const float*)d_in[0];
    const float* W1 = (const float*)d_in[1];
    const float* b1 = (const float*)d_in[2];
    const float* W2 = (const float*)d_in[3];
    const float* b2 = (const float*)d_in[4];
    const float* W3 = (const float*)d_in[5];
    const float* b3 = (const float*)d_in[6];
    float* out = (float*)d_out;

    __nv_bfloat16 *xh, *xl, *w1h, *w1l, *w2h, *w2l, *w3h, *w3l;
    __nv_bfloat16 *qh, *ql, *kh, *kl, *vh, *vl, *sh, *sl;
    float* S;
    cudaGetSymbolAddress((void**)&xh, g_xh);   cudaGetSymbolAddress((void**)&xl, g_xl);
    cudaGetSymbolAddress((void**)&w1h, g_w1h); cudaGetSymbolAddress((void**)&w1l, g_w1l);
    cudaGetSymbolAddress((void**)&w2h, g_w2h); cudaGetSymbolAddress((void**)&w2l, g_w2l);
    cudaGetSymbolAddress((void**)&w3h, g_w3h); cudaGetSymbolAddress((void**)&w3l, g_w3l);
    cudaGetSymbolAddress((void**)&qh, g_qh);   cudaGetSymbolAddress((void**)&ql, g_ql);
    cudaGetSymbolAddress((void**)&kh, g_kh);   cudaGetSymbolAddress((void**)&kl, g_kl);
    cudaGetSymbolAddress((void**)&vh, g_vh);   cudaGetSymbolAddress((void**)&vl, g_vl);
    cudaGetSymbolAddress((void**)&sh, g_sh);   cudaGetSymbolAddress((void**)&sl, g_sl);
    cudaGetSymbolAddress((void**)&S, g_S);

    cudaFuncSetAttribute(mma_gemm<true, true, false, true, true>,
                         cudaFuncAttributeMaxDynamicSharedMemorySize, GM_SMEM(true));
    cudaFuncSetAttribute(mma_gemm<true, false, true, false, false>,
                         cudaFuncAttributeMaxDynamicSharedMemorySize, GM_SMEM(true));
    cudaFuncSetAttribute(mma_gemm<false, false, true, false, false>,
                         cudaFuncAttributeMaxDynamicSharedMemorySize, GM_SMEM(false));

    const dim3 blk(256);

    const int nx4 = N_TOK * D_MODEL / 4;
    const int nw4 = D_MODEL * D_MODEL / 4;
    split_kernel<<<(nx4 + 255) / 256, blk>>>(x, xh, xl, nx4);
    split3_kernel<<<dim3((nw4 + 255) / 256, 3), blk>>>(
        W1, w1h, w1l, W2, w2h, w2l, W3, w3h, w3l, nw4);

    const dim3 grid_qkv(D_MODEL / 128, N_TOK / 128, 3);  // (8, 32, 3)
    const dim3 grid_attn(N_TOK / 128, N_TOK / 128);      // (32, 32)
    const dim3 grid_pv(D_MODEL / 128, N_TOK / 128);      // (8, 32)

    // merged Q/K/V projections (bf16 hi/lo out, +bias)
    mma_gemm<true, true, false, true, true><<<grid_qkv, blk, GM_SMEM(true)>>>(
        xh, xl, w1h, w1l, w2h, w2l, w3h, w3l, b1, b2, b3,
        nullptr, qh, ql, kh, kl, vh, vl, N_TOK, D_MODEL, D_MODEL, 1.f);

    // S = scale * K @ Q^T  (fp32 out)
    const float scale = rsqrtf((float)D_MODEL);
    mma_gemm<true, false, true, false, false><<<grid_attn, blk, GM_SMEM(true)>>>(
        kh, kl, qh, ql, nullptr, nullptr, nullptr, nullptr, nullptr, nullptr, nullptr,
        S, nullptr, nullptr, nullptr, nullptr, nullptr, nullptr,
        N_TOK, N_TOK, D_MODEL, scale);

    // softmax rows -> bf16 hi/lo probabilities
    softmax_split<<<N_TOK, blk>>>(S, sh, sl);

    // out = P @ V (fp32 out)
    mma_gemm<false, false, true, false, false><<<grid_pv, blk, GM_SMEM(false)>>>(
        sh, sl, vh, vl, nullptr, nullptr, nullptr, nullptr, nullptr, nullptr, nullptr,
        out, nullptr, nullptr, nullptr, nullptr, nullptr, nullptr,
        N_TOK, D_MODEL, N_TOK, 1.f);
}